// round 4
// baseline (speedup 1.0000x reference)
#include <cuda_runtime.h>
#include <math_constants.h>

#define Bn 128
#define Hn 1024
#define Sn 512
#define VOUT 50000
#define VIN 32000

// ---------------- scratch (device globals: no allocs allowed) ----------------
__device__ float g_logits[Bn * VOUT];    // 25.6 MB
__device__ float g_inpdist[Bn * VIN];    // 16.4 MB
__device__ int   g_inv[VOUT];            // winning (last) input-vocab index per output id
__device__ float g_rowmax[Bn];
__device__ float g_rowsum[Bn];

// ---------------------------------------------------------------------------
__device__ __forceinline__ void atomicMaxFloat(float* addr, float val) {
    int* ia = (int*)addr;
    int old = *ia;
    while (__int_as_float(old) < val) {
        int assumed = old;
        old = atomicCAS(ia, assumed, __float_as_int(val));
        if (old == assumed) break;
    }
}

// K0: reset scratch
__global__ void k_init() {
    int i = blockIdx.x * blockDim.x + threadIdx.x;
    if (i < Bn * VIN) g_inpdist[i] = 0.0f;
    if (i < VOUT)     g_inv[i] = -1;
    if (i < Bn)       g_rowmax[i] = -CUDART_INF_F;
}

// K1: inv[v] = max i with inp_to_act[i]==v  (XLA scatter-set: last index wins)
__global__ void k_inv(const int* __restrict__ inp_to_act) {
    int i = blockIdx.x * blockDim.x + threadIdx.x;
    if (i < VIN) atomicMax(&g_inv[inp_to_act[i]], i);
}

// K2: attention softmax (write output) + scatter-add onto input vocab
__global__ void __launch_bounds__(256) k_attn(const float* __restrict__ attn,
                                              const int* __restrict__ inptensor,
                                              float* __restrict__ out_attn) {
    __shared__ float red[256];
    int b = blockIdx.x, t = threadIdx.x;
    float v0 = attn[b * Sn + t];
    float v1 = attn[b * Sn + t + 256];
    red[t] = fmaxf(v0, v1);
    __syncthreads();
    for (int o = 128; o > 0; o >>= 1) {
        if (t < o) red[t] = fmaxf(red[t], red[t + o]);
        __syncthreads();
    }
    float m = red[0];
    __syncthreads();
    // exact expf here: attn_probs are an output with tight row-sum structure
    float e0 = expf(v0 - m), e1 = expf(v1 - m);
    red[t] = e0 + e1;
    __syncthreads();
    for (int o = 128; o > 0; o >>= 1) {
        if (t < o) red[t] += red[t + o];
        __syncthreads();
    }
    float inv = 1.0f / red[0];
    float p0 = e0 * inv, p1 = e1 * inv;
    out_attn[b * Sn + t]       = p0;
    out_attn[b * Sn + t + 256] = p1;
    atomicAdd(&g_inpdist[b * VIN + inptensor[b * Sn + t]],       p0);
    atomicAdd(&g_inpdist[b * VIN + inptensor[b * Sn + t + 256]], p1);
}

// K3: copy-or-generate gate probs (needs g_inv)
__global__ void __launch_bounds__(256) k_pog(const float* __restrict__ x,
                                             const float* __restrict__ cog_W,
                                             const float* __restrict__ cog_b,
                                             const float* __restrict__ out_mask,
                                             float* __restrict__ out_pog) {
    __shared__ float r0[256], r1[256], rc[256];
    int b = blockIdx.x, t = threadIdx.x;
    float s0 = 0.f, s1 = 0.f, c = 0.f;
    for (int h = t; h < Hn; h += 256) {
        float xv = x[b * Hn + h];
        s0 = fmaf(xv, cog_W[h], s0);
        s1 = fmaf(xv, cog_W[Hn + h], s1);
    }
    for (int v = t; v < VOUT; v += 256) {
        if (g_inv[v] >= 0 && v != 0) c += out_mask[b * VOUT + v];
    }
    r0[t] = s0; r1[t] = s1; rc[t] = c;
    __syncthreads();
    for (int o = 128; o > 0; o >>= 1) {
        if (t < o) { r0[t] += r0[t + o]; r1[t] += r1[t + o]; rc[t] += rc[t + o]; }
        __syncthreads();
    }
    if (t == 0) {
        float l0 = r0[0] + cog_b[0];
        float l1 = r1[0] + cog_b[1];
        if (!(rc[0] > 0.0f)) l1 = -CUDART_INF_F;
        float m = fmaxf(l0, l1);
        float e0 = expf(l0 - m), e1 = expf(l1 - m);
        float is = 1.0f / (e0 + e1);
        out_pog[b * 2 + 0] = e0 * is;
        out_pog[b * 2 + 1] = e1 * is;
    }
}

// K4: main GEMM  logits[b,v] = x[b]·W[v] + gen_b[v] + log(out_mask[b,v]); track rowmax
// Tiles: BM=128 (all rows), BN=128, BK=16; 256 threads; 8x8 per-thread tile.
__global__ void __launch_bounds__(256) k_gemm(const float* __restrict__ x,
                                              const float* __restrict__ W,
                                              const float* __restrict__ gb,
                                              const float* __restrict__ om) {
    __shared__ float As[16][132];   // [k][m]  (row stride 528B: 16B-aligned)
    __shared__ float Ws[16][132];   // [k][n]
    __shared__ float red[128][17];  // per-row block max

    const int t  = threadIdx.x;
    const int n0 = blockIdx.x * 128;
    const int tx = t & 15;          // 16 col groups * 8 cols
    const int ty = t >> 4;          // 16 row groups * 8 rows

    float acc[8][8];
#pragma unroll
    for (int i = 0; i < 8; i++)
#pragma unroll
        for (int j = 0; j < 8; j++) acc[i][j] = 0.f;

    for (int k0 = 0; k0 < Hn; k0 += 16) {
        // A tile: 128x16 = 512 float4, 2 per thread
#pragma unroll
        for (int p = 0; p < 2; p++) {
            int idx = t + p * 256;
            int m = idx >> 2, f = idx & 3;
            float4 v = *reinterpret_cast<const float4*>(&x[m * Hn + k0 + f * 4]);
            As[f * 4 + 0][m] = v.x; As[f * 4 + 1][m] = v.y;
            As[f * 4 + 2][m] = v.z; As[f * 4 + 3][m] = v.w;
        }
        // W tile: 128x16 = 512 float4, 2 per thread (guard tail block)
#pragma unroll
        for (int p = 0; p < 2; p++) {
            int idx = t + p * 256;
            int n = idx >> 2, f = idx & 3;
            int gn = n0 + n;
            float4 v = make_float4(0.f, 0.f, 0.f, 0.f);
            if (gn < VOUT)
                v = *reinterpret_cast<const float4*>(&W[gn * Hn + k0 + f * 4]);
            Ws[f * 4 + 0][n] = v.x; Ws[f * 4 + 1][n] = v.y;
            Ws[f * 4 + 2][n] = v.z; Ws[f * 4 + 3][n] = v.w;
        }
        __syncthreads();
#pragma unroll
        for (int k = 0; k < 16; k++) {
            // vectorized fragment loads: 4x LDS.128 instead of 16x LDS.32
            float4 a0 = *reinterpret_cast<const float4*>(&As[k][ty * 8]);
            float4 a1 = *reinterpret_cast<const float4*>(&As[k][ty * 8 + 4]);
            float4 w0 = *reinterpret_cast<const float4*>(&Ws[k][tx * 8]);
            float4 w1 = *reinterpret_cast<const float4*>(&Ws[k][tx * 8 + 4]);
            float a[8] = {a0.x, a0.y, a0.z, a0.w, a1.x, a1.y, a1.z, a1.w};
            float w[8] = {w0.x, w0.y, w0.z, w0.w, w1.x, w1.y, w1.z, w1.w};
#pragma unroll
            for (int i = 0; i < 8; i++)
#pragma unroll
                for (int j = 0; j < 8; j++) acc[i][j] = fmaf(a[i], w[j], acc[i][j]);
        }
        __syncthreads();
    }

    // epilogue: + bias + log(mask), store logits, block/global rowmax
    bool full = (n0 + 128 <= VOUT);
#pragma unroll
    for (int i = 0; i < 8; i++) {
        int m = ty * 8 + i;
        float rm = -CUDART_INF_F;
        float vals[8];
#pragma unroll
        for (int j = 0; j < 8; j++) {
            int n = n0 + tx * 8 + j;
            if (n < VOUT) {
                float mask = om[m * VOUT + n];
                // __logf: MUFU LG2-based, ~2^-21 rel err — well inside 1e-3 gate
                float val = acc[i][j] + gb[n] + __logf(mask);
                vals[j] = val;
                rm = fmaxf(rm, val);
            }
        }
        if (full) {
            float4 s0 = make_float4(vals[0], vals[1], vals[2], vals[3]);
            float4 s1 = make_float4(vals[4], vals[5], vals[6], vals[7]);
            *reinterpret_cast<float4*>(&g_logits[m * VOUT + n0 + tx * 8])     = s0;
            *reinterpret_cast<float4*>(&g_logits[m * VOUT + n0 + tx * 8 + 4]) = s1;
        } else {
#pragma unroll
            for (int j = 0; j < 8; j++) {
                int n = n0 + tx * 8 + j;
                if (n < VOUT) g_logits[m * VOUT + n] = vals[j];
            }
        }
        red[m][tx] = rm;
    }
    __syncthreads();
    if (t < 128) {
        float rm = red[t][0];
#pragma unroll
        for (int q = 1; q < 16; q++) rm = fmaxf(rm, red[t][q]);
        atomicMaxFloat(&g_rowmax[t], rm);
    }
}

// K5: rowsum of exp(logits - rowmax)
__global__ void __launch_bounds__(256) k_rowsum() {
    __shared__ float red[256];
    int b = blockIdx.x, t = threadIdx.x;
    float m = g_rowmax[b];
    float s = 0.f;
    for (int v = t; v < VOUT; v += 256) s += __expf(g_logits[b * VOUT + v] - m);
    red[t] = s;
    __syncthreads();
    for (int o = 128; o > 0; o >>= 1) {
        if (t < o) red[t] += red[t + o];
        __syncthreads();
    }
    if (t == 0) g_rowsum[b] = red[0];
}

// K6: combine -> gen_probs and out_probs
__global__ void __launch_bounds__(256) k_combine(const float* __restrict__ out_pog,
                                                 float* __restrict__ out_final,
                                                 float* __restrict__ out_gen) {
    int b = blockIdx.y;
    int v = blockIdx.x * 256 + threadIdx.x;
    if (v >= VOUT) return;
    int idx = b * VOUT + v;
    float m  = g_rowmax[b];
    float is = 1.0f / g_rowsum[b];
    float g  = __expf(g_logits[idx] - m) * is;
    int iv = g_inv[v];
    float ptr = (iv >= 0) ? g_inpdist[b * VIN + iv] : 0.0f;
    float p0 = __ldg(&out_pog[b * 2 + 0]);
    float p1 = __ldg(&out_pog[b * 2 + 1]);
    out_gen[idx]   = g;
    out_final[idx] = __logf(p0 * g + p1 * ptr);
}

// ---------------------------------------------------------------------------
extern "C" void kernel_launch(void* const* d_in, const int* in_sizes, int n_in,
                              void* d_out, int out_size) {
    const float* x          = (const float*)d_in[0];
    const int*   inptensor  = (const int*)d_in[1];
    const float* attn       = (const float*)d_in[2];
    const float* out_mask   = (const float*)d_in[3];
    const float* gen_W      = (const float*)d_in[4];
    const float* gen_b      = (const float*)d_in[5];
    const float* cog_W      = (const float*)d_in[6];
    const float* cog_b      = (const float*)d_in[7];
    const int*   inp_to_act = (const int*)d_in[8];

    float* out        = (float*)d_out;
    float* out_final  = out;                                   // (B, VOUT)
    float* out_pog    = out + (size_t)Bn * VOUT;               // (B, 2)
    float* out_gen    = out_pog + (size_t)Bn * 2;              // (B, VOUT)
    float* out_attn   = out_gen + (size_t)Bn * VOUT;           // (B, S)

    k_init<<<(Bn * VIN + 255) / 256, 256>>>();
    k_inv<<<(VIN + 255) / 256, 256>>>(inp_to_act);
    k_attn<<<Bn, 256>>>(attn, inptensor, out_attn);
    k_pog<<<Bn, 256>>>(x, cog_W, cog_b, out_mask, out_pog);
    k_gemm<<<(VOUT + 127) / 128, 256>>>(x, gen_W, gen_b, out_mask);
    k_rowsum<<<Bn, 256>>>();
    dim3 cg((VOUT + 255) / 256, Bn);
    k_combine<<<cg, 256>>>(out_pog, out_final, out_gen);
}

// round 6
// speedup vs baseline: 2.2046x; 2.2046x over previous
#include <cuda_runtime.h>
#include <cuda_bf16.h>
#include <math_constants.h>

#define Bn 128
#define Hn 1024
#define Sn 512
#define VOUT 50000
#define VIN 32000

// ---------------- scratch (device globals: no allocs allowed) ----------------
__device__ float g_logits[Bn * VOUT];    // 25.6 MB
__device__ float g_inpdist[Bn * VIN];    // 16.4 MB
__device__ int   g_inv[VOUT];
__device__ float g_rowmax[Bn];
__device__ float g_rowsum[Bn];
__device__ float g_cancopy[Bn];

// ---------------------------------------------------------------------------
__device__ __forceinline__ void atomicMaxFloat(float* addr, float val) {
    int* ia = (int*)addr;
    int old = *ia;
    while (__int_as_float(old) < val) {
        int assumed = old;
        old = atomicCAS(ia, assumed, __float_as_int(val));
        if (old == assumed) break;
    }
}

// K0: reset scratch
__global__ void k_init() {
    int i = blockIdx.x * blockDim.x + threadIdx.x;
    if (i < Bn * VIN) g_inpdist[i] = 0.0f;
    if (i < VOUT)     g_inv[i] = -1;
    if (i < Bn)     { g_rowmax[i] = -CUDART_INF_F; g_cancopy[i] = 0.0f; }
}

// K1: inv[v] = max i with inp_to_act[i]==v  (XLA scatter-set: last index wins)
__global__ void k_inv(const int* __restrict__ inp_to_act) {
    int i = blockIdx.x * blockDim.x + threadIdx.x;
    if (i < VIN) atomicMax(&g_inv[inp_to_act[i]], i);
}

// K2: attention softmax (write output) + scatter-add onto input vocab
__global__ void __launch_bounds__(256) k_attn(const float* __restrict__ attn,
                                              const int* __restrict__ inptensor,
                                              float* __restrict__ out_attn) {
    __shared__ float red[256];
    int b = blockIdx.x, t = threadIdx.x;
    float v0 = attn[b * Sn + t];
    float v1 = attn[b * Sn + t + 256];
    red[t] = fmaxf(v0, v1);
    __syncthreads();
    for (int o = 128; o > 0; o >>= 1) {
        if (t < o) red[t] = fmaxf(red[t], red[t + o]);
        __syncthreads();
    }
    float m = red[0];
    __syncthreads();
    float e0 = expf(v0 - m), e1 = expf(v1 - m);
    red[t] = e0 + e1;
    __syncthreads();
    for (int o = 128; o > 0; o >>= 1) {
        if (t < o) red[t] += red[t + o];
        __syncthreads();
    }
    float inv = 1.0f / red[0];
    float p0 = e0 * inv, p1 = e1 * inv;
    out_attn[b * Sn + t]       = p0;
    out_attn[b * Sn + t + 256] = p1;
    atomicAdd(&g_inpdist[b * VIN + inptensor[b * Sn + t]],       p0);
    atomicAdd(&g_inpdist[b * VIN + inptensor[b * Sn + t + 256]], p1);
}

// K2b: cancopy[b] = sum_v (copyable(v) * out_mask[b,v]) — parallel over (b, v-chunk)
__global__ void __launch_bounds__(256) k_cancopy(const float* __restrict__ om) {
    int b = blockIdx.y;
    int v0 = blockIdx.x * 1024 + threadIdx.x;
    float c = 0.f;
#pragma unroll
    for (int p = 0; p < 4; p++) {
        int v = v0 + p * 256;
        if (v < VOUT && v != 0 && g_inv[v] >= 0) c += om[(size_t)b * VOUT + v];
    }
#pragma unroll
    for (int o = 16; o > 0; o >>= 1) c += __shfl_xor_sync(0xffffffffu, c, o);
    __shared__ float ws[8];
    int w = threadIdx.x >> 5;
    if ((threadIdx.x & 31) == 0) ws[w] = c;
    __syncthreads();
    if (threadIdx.x == 0) {
        float s = 0.f;
#pragma unroll
        for (int i = 0; i < 8; i++) s += ws[i];
        atomicAdd(&g_cancopy[b], s);
    }
}

// K3: copy-or-generate gate probs (tiny now: just the two dot products)
__global__ void __launch_bounds__(256) k_pog(const float* __restrict__ x,
                                             const float* __restrict__ cog_W,
                                             const float* __restrict__ cog_b,
                                             float* __restrict__ out_pog) {
    __shared__ float r0[256], r1[256];
    int b = blockIdx.x, t = threadIdx.x;
    float s0 = 0.f, s1 = 0.f;
    for (int h = t; h < Hn; h += 256) {
        float xv = x[b * Hn + h];
        s0 = fmaf(xv, cog_W[h], s0);
        s1 = fmaf(xv, cog_W[Hn + h], s1);
    }
    r0[t] = s0; r1[t] = s1;
    __syncthreads();
    for (int o = 128; o > 0; o >>= 1) {
        if (t < o) { r0[t] += r0[t + o]; r1[t] += r1[t + o]; }
        __syncthreads();
    }
    if (t == 0) {
        float l0 = r0[0] + cog_b[0];
        float l1 = r1[0] + cog_b[1];
        if (!(g_cancopy[b] > 0.0f)) l1 = -CUDART_INF_F;
        float m = fmaxf(l0, l1);
        float e0 = expf(l0 - m), e1 = expf(l1 - m);
        float is = 1.0f / (e0 + e1);
        out_pog[b * 2 + 0] = e0 * is;
        out_pog[b * 2 + 1] = e1 * is;
    }
}

// ------------------- K4: tensor-core GEMM (bf16 3x split) -------------------
// logits[m,v] = x[m]·W[v] + gen_b[v] + log(out_mask[m,v]); track rowmax.
// BM=128 (all batch rows), BN=128, k-chunk 16; 256 threads = 8 warps (2m x 4n),
// each warp owns 64x32 via 4x4 m16n8k16 tiles. Split: x=xh+xl, W=Wh+Wl (bf16);
// acc += xh*Wh + xh*Wl + xl*Wh  (error ~2^-17 per product).

#define MMA_BF16(d, a, b) \
    asm volatile("mma.sync.aligned.m16n8k16.row.col.f32.bf16.bf16.f32 " \
                 "{%0,%1,%2,%3},{%4,%5,%6,%7},{%8,%9},{%0,%1,%2,%3};" \
                 : "+f"((d)[0]), "+f"((d)[1]), "+f"((d)[2]), "+f"((d)[3]) \
                 : "r"((a)[0]), "r"((a)[1]), "r"((a)[2]), "r"((a)[3]), \
                   "r"((b)[0]), "r"((b)[1]))

// split a float4 (4 consecutive k at one row) into hi/lo bf16x2 pairs and store.
// Row stride = 24 bf16 = 12 words (conflict-free for fragment loads).
__device__ __forceinline__ void store_split(unsigned* Sh, unsigned* Sl,
                                            int row, int fc, float4 v) {
    __nv_bfloat162 h01 = __float22bfloat162_rn(make_float2(v.x, v.y));
    __nv_bfloat162 h23 = __float22bfloat162_rn(make_float2(v.z, v.w));
    float2 hb01 = __bfloat1622float2(h01);
    float2 hb23 = __bfloat1622float2(h23);
    __nv_bfloat162 l01 = __float22bfloat162_rn(make_float2(v.x - hb01.x, v.y - hb01.y));
    __nv_bfloat162 l23 = __float22bfloat162_rn(make_float2(v.z - hb23.x, v.w - hb23.y));
    int w = row * 12 + fc * 2;   // even -> 8B aligned
    *reinterpret_cast<uint2*>(&Sh[w]) =
        make_uint2(*reinterpret_cast<unsigned*>(&h01), *reinterpret_cast<unsigned*>(&h23));
    *reinterpret_cast<uint2*>(&Sl[w]) =
        make_uint2(*reinterpret_cast<unsigned*>(&l01), *reinterpret_cast<unsigned*>(&l23));
}

__global__ void __launch_bounds__(256) k_gemm_mma(const float* __restrict__ x,
                                                  const float* __restrict__ W,
                                                  const float* __restrict__ gb,
                                                  const float* __restrict__ om) {
    __shared__ __align__(16) unsigned sAh[128 * 12], sAl[128 * 12];
    __shared__ __align__(16) unsigned sWh[128 * 12], sWl[128 * 12];

    const int t = threadIdx.x;
    const int lane = t & 31, wid = t >> 5;
    const int g = lane >> 2, tig = lane & 3;
    const int warp_m = wid & 1, warp_n = wid >> 1;
    const int n0 = blockIdx.x * 128;

    // gmem staging: each thread loads 2 float4 per matrix per chunk
    const int lrow = t >> 2;            // 0..63
    const int lfc  = t & 3;             // 0..3
    const float* xa = x + (size_t)lrow * Hn + lfc * 4;
    const float* xb = x + (size_t)(lrow + 64) * Hn + lfc * 4;
    const int wr0 = n0 + lrow, wr1 = n0 + lrow + 64;
    const bool v0 = wr0 < VOUT, v1 = wr1 < VOUT;
    const float* wa = W + (size_t)(v0 ? wr0 : 0) * Hn + lfc * 4;
    const float* wb = W + (size_t)(v1 ? wr1 : 0) * Hn + lfc * 4;

    float4 sa0 = *reinterpret_cast<const float4*>(xa);
    float4 sa1 = *reinterpret_cast<const float4*>(xb);
    float4 sw0 = v0 ? *reinterpret_cast<const float4*>(wa) : make_float4(0, 0, 0, 0);
    float4 sw1 = v1 ? *reinterpret_cast<const float4*>(wb) : make_float4(0, 0, 0, 0);

    float acc[4][4][4];
#pragma unroll
    for (int i = 0; i < 4; i++)
#pragma unroll
        for (int j = 0; j < 4; j++)
#pragma unroll
            for (int q = 0; q < 4; q++) acc[i][j][q] = 0.f;

    for (int kc = 0; kc < Hn / 16; kc++) {
        store_split(sAh, sAl, lrow,      lfc, sa0);
        store_split(sAh, sAl, lrow + 64, lfc, sa1);
        store_split(sWh, sWl, lrow,      lfc, sw0);
        store_split(sWh, sWl, lrow + 64, lfc, sw1);
        __syncthreads();
        if (kc < Hn / 16 - 1) {
            xa += 16; xb += 16; wa += 16; wb += 16;
            sa0 = *reinterpret_cast<const float4*>(xa);
            sa1 = *reinterpret_cast<const float4*>(xb);
            sw0 = v0 ? *reinterpret_cast<const float4*>(wa) : make_float4(0, 0, 0, 0);
            sw1 = v1 ? *reinterpret_cast<const float4*>(wb) : make_float4(0, 0, 0, 0);
        }

        unsigned bh[4][2], bl[4][2];
#pragma unroll
        for (int j = 0; j < 4; j++) {
            int nr = warp_n * 32 + j * 8 + g;
            bh[j][0] = sWh[nr * 12 + tig];
            bh[j][1] = sWh[nr * 12 + tig + 4];
            bl[j][0] = sWl[nr * 12 + tig];
            bl[j][1] = sWl[nr * 12 + tig + 4];
        }
#pragma unroll
        for (int i = 0; i < 4; i++) {
            int mr = warp_m * 64 + i * 16 + g;
            unsigned ah[4], al[4];
            ah[0] = sAh[mr * 12 + tig];        ah[1] = sAh[(mr + 8) * 12 + tig];
            ah[2] = sAh[mr * 12 + tig + 4];    ah[3] = sAh[(mr + 8) * 12 + tig + 4];
            al[0] = sAl[mr * 12 + tig];        al[1] = sAl[(mr + 8) * 12 + tig];
            al[2] = sAl[mr * 12 + tig + 4];    al[3] = sAl[(mr + 8) * 12 + tig + 4];
#pragma unroll
            for (int j = 0; j < 4; j++) {
                MMA_BF16(acc[i][j], ah, bh[j]);
                MMA_BF16(acc[i][j], ah, bl[j]);
                MMA_BF16(acc[i][j], al, bh[j]);
            }
        }
        __syncthreads();
    }

    // epilogue: + bias + log(mask), store logits, rowmax via shfl + global atomic
#pragma unroll
    for (int i = 0; i < 4; i++) {
        int r0 = warp_m * 64 + i * 16 + g;
        int r1 = r0 + 8;
        float rm0 = -CUDART_INF_F, rm1 = -CUDART_INF_F;
#pragma unroll
        for (int j = 0; j < 4; j++) {
            int c = n0 + warp_n * 32 + j * 8 + 2 * tig;
            if (c < VOUT) {
                float b0 = gb[c], b1 = gb[c + 1];
                float va = acc[i][j][0] + b0 + __logf(om[(size_t)r0 * VOUT + c]);
                float vb = acc[i][j][1] + b1 + __logf(om[(size_t)r0 * VOUT + c + 1]);
                float vc = acc[i][j][2] + b0 + __logf(om[(size_t)r1 * VOUT + c]);
                float vd = acc[i][j][3] + b1 + __logf(om[(size_t)r1 * VOUT + c + 1]);
                *reinterpret_cast<float2*>(&g_logits[(size_t)r0 * VOUT + c]) = make_float2(va, vb);
                *reinterpret_cast<float2*>(&g_logits[(size_t)r1 * VOUT + c]) = make_float2(vc, vd);
                rm0 = fmaxf(rm0, fmaxf(va, vb));
                rm1 = fmaxf(rm1, fmaxf(vc, vd));
            }
        }
        rm0 = fmaxf(rm0, __shfl_xor_sync(0xffffffffu, rm0, 1));
        rm0 = fmaxf(rm0, __shfl_xor_sync(0xffffffffu, rm0, 2));
        rm1 = fmaxf(rm1, __shfl_xor_sync(0xffffffffu, rm1, 1));
        rm1 = fmaxf(rm1, __shfl_xor_sync(0xffffffffu, rm1, 2));
        if (tig == 0) {
            atomicMaxFloat(&g_rowmax[r0], rm0);
            atomicMaxFloat(&g_rowmax[r1], rm1);
        }
    }
}

// K5: rowsum of exp(logits - rowmax)
__global__ void __launch_bounds__(256) k_rowsum() {
    __shared__ float red[256];
    int b = blockIdx.x, t = threadIdx.x;
    float m = g_rowmax[b];
    float s = 0.f;
    for (int v = t; v < VOUT; v += 256) s += __expf(g_logits[b * VOUT + v] - m);
    red[t] = s;
    __syncthreads();
    for (int o = 128; o > 0; o >>= 1) {
        if (t < o) red[t] += red[t + o];
        __syncthreads();
    }
    if (t == 0) g_rowsum[b] = red[0];
}

// K6: combine -> gen_probs and out_probs
__global__ void __launch_bounds__(256) k_combine(const float* __restrict__ out_pog,
                                                 float* __restrict__ out_final,
                                                 float* __restrict__ out_gen) {
    int b = blockIdx.y;
    int v = blockIdx.x * 256 + threadIdx.x;
    if (v >= VOUT) return;
    int idx = b * VOUT + v;
    float m  = g_rowmax[b];
    float is = 1.0f / g_rowsum[b];
    float g  = __expf(g_logits[idx] - m) * is;
    int iv = g_inv[v];
    float ptr = (iv >= 0) ? g_inpdist[b * VIN + iv] : 0.0f;
    float p0 = __ldg(&out_pog[b * 2 + 0]);
    float p1 = __ldg(&out_pog[b * 2 + 1]);
    out_gen[idx]   = g;
    out_final[idx] = __logf(p0 * g + p1 * ptr);
}

// ---------------------------------------------------------------------------
extern "C" void kernel_launch(void* const* d_in, const int* in_sizes, int n_in,
                              void* d_out, int out_size) {
    const float* x          = (const float*)d_in[0];
    const int*   inptensor  = (const int*)d_in[1];
    const float* attn       = (const float*)d_in[2];
    const float* out_mask   = (const float*)d_in[3];
    const float* gen_W      = (const float*)d_in[4];
    const float* gen_b      = (const float*)d_in[5];
    const float* cog_W      = (const float*)d_in[6];
    const float* cog_b      = (const float*)d_in[7];
    const int*   inp_to_act = (const int*)d_in[8];

    float* out        = (float*)d_out;
    float* out_final  = out;                                   // (B, VOUT)
    float* out_pog    = out + (size_t)Bn * VOUT;               // (B, 2)
    float* out_gen    = out_pog + (size_t)Bn * 2;              // (B, VOUT)
    float* out_attn   = out_gen + (size_t)Bn * VOUT;           // (B, S)

    k_init<<<(Bn * VIN + 255) / 256, 256>>>();
    k_inv<<<(VIN + 255) / 256, 256>>>(inp_to_act);
    k_attn<<<Bn, 256>>>(attn, inptensor, out_attn);
    dim3 cc((VOUT + 1023) / 1024, Bn);
    k_cancopy<<<cc, 256>>>(out_mask);
    k_pog<<<Bn, 256>>>(x, cog_W, cog_b, out_pog);
    k_gemm_mma<<<(VOUT + 127) / 128, 256>>>(x, gen_W, gen_b, out_mask);
    k_rowsum<<<Bn, 256>>>();
    dim3 cg((VOUT + 255) / 256, Bn);
    k_combine<<<cg, 256>>>(out_pog, out_final, out_gen);
}